// round 10
// baseline (speedup 1.0000x reference)
#include <cuda_runtime.h>
#include <math.h>

// ---------------- dims ----------------
#define NFE 212992              // 8*13*32*64
#define NHE 1064960             // 8*65*32*64
#define NOE 4194304             // 8*256*32*64
#define GSTG 416                // NFE/4/128 : 128-thread blocks, 4 elems/thread

// ---------------- physics consts ----------------
#define DTs    300.0f
#define KHc    15.0f
#define KVc    0.1f
#define LVc    2.5e6f
#define CPc    1005.0f
#define RGASc  8.314f
#define RDc    287.0f
#define OMEGAc 7.29e-5f
#define EMISc  0.7f
#define SIGMAc 5.67e-8f
#define PIXYc  ((float)(M_PI * 6371000.0 / 33.0))

__constant__ float c_DZ[13]  = {50.f,50.f,50.f,50.f,50.f,75.f,100.f,100.f,100.f,125.f,112.f,75.f,75.f};
__constant__ float c_PRS[13] = {50.f,100.f,150.f,200.f,250.f,300.f,400.f,500.f,600.f,700.f,850.f,925.f,1000.f};

// ---------------- scratch ----------------
__device__ float g_h[NHE], g_o65[NHE];
__device__ float g_o2[NOE];
__device__ float g_fld[5][NFE];                        // z,q,u,v,t post-BN
__device__ float g_zx[NFE], g_zy[NFE], g_zz[NFE], g_ux[NFE], g_vy[NFE];
__device__ float g_w[NFE], g_rate[NFE];
__device__ float g_sua[NFE], g_sva[NFE], g_sta[NFE];   // RK stage fields u,v,t
__device__ float g_accu[NFE], g_accv[NFE], g_acct[NFE];
__device__ float g_k4t[NFE], g_dq[NFE], g_dzd[NFE];
__device__ float g_m65[65], g_is65[65], g_m256[256], g_is256[256];
__device__ float g_red[27];
__device__ float g_redp[27][32];                       // sub-slotted reductions
__device__ float g_invpx[32], g_fcor[32];
__device__ float g_Wy[32][9];                          // composite d_y(d_y) band
__device__ float g_Wz[13][9];                          // composite d_z(d_z) band

// red slots: 0..4 field min (z,q,u,v,t); 5..9 field max; 10..14 field sum;
//            15 sarg min; 16 sarg max; 17..21 diff min (z,q,u,v,t); 22..26 diff max

// ---------------- helpers ----------------
__device__ __forceinline__ void atomicMinF(float* a, float v) {
    if (v >= 0.f) atomicMin((int*)a, __float_as_int(v));
    else          atomicMax((unsigned int*)a, __float_as_uint(v));
}
__device__ __forceinline__ void atomicMaxF(float* a, float v) {
    if (v >= 0.f) atomicMax((int*)a, __float_as_int(v));
    else          atomicMin((unsigned int*)a, __float_as_uint(v));
}
__device__ __forceinline__ float avoid_inf1(float t) {
    if (t == 0.f) return 1.f;
    if (fabsf(t) < 1.f) return t > 0.f ? 1.f : -1.f;
    return t;
}

typedef unsigned long long u64;
__device__ __forceinline__ u64 pk2(float lo, float hi) {
    u64 r; asm("mov.b64 %0,{%1,%2};" : "=l"(r) : "f"(lo), "f"(hi)); return r;
}
__device__ __forceinline__ void fm2(u64& d, u64 a, u64 b) {
    asm("fma.rn.f32x2 %0,%1,%2,%0;" : "+l"(d) : "l"(a), "l"(b));
}
__device__ __forceinline__ void upk2(float& lo, float& hi, u64 v) {
    asm("mov.b64 {%0,%1},%2;" : "=f"(lo), "=f"(hi) : "l"(v));
}
__device__ __forceinline__ u64 oddpair(u64 a, u64 b) {
    u64 r;
    asm("{\n\t.reg .f32 al, ah, bl, bh;\n\t"
        "mov.b64 {al,ah}, %1;\n\t"
        "mov.b64 {bl,bh}, %2;\n\t"
        "mov.b64 %0, {ah,bl};\n\t}"
        : "=l"(r) : "l"(a), "l"(b));
    return r;
}

__device__ __forceinline__ int pidxN(int m, int n) {   // block-replicate pad index
    return m < 2 ? m : (m < n + 2 ? m - 2 : m - 4);
}

// ---------------- 4-wide packet ----------------
struct P4 { int i, v, h, w0; };
__device__ __forceinline__ P4 decode4(int i4) {
    P4 p; int i = i4 << 2;
    p.i = i; p.w0 = i & 63; p.h = (i >> 6) & 31;
    p.v = (i >> 11) % 13;
    return p;
}
__device__ __forceinline__ void ld4(float* d, const float* __restrict__ f, int idx) {
    float4 t = *reinterpret_cast<const float4*>(f + idx);
    d[0] = t.x; d[1] = t.y; d[2] = t.z; d[3] = t.w;
}
__device__ __forceinline__ void st4(float* f, int idx, const float* s) {
    *reinterpret_cast<float4*>(f + idx) = make_float4(s[0], s[1], s[2], s[3]);
}
__device__ __forceinline__ void dx4(float* out, const float* __restrict__ f,
                                    const P4& p, float invpx) {
    float win[12];
    int rb = p.i - p.w0;
    ld4(win,     f, rb + ((p.w0 + 60) & 63));
    ld4(win + 4, f, p.i);
    ld4(win + 8, f, rb + ((p.w0 + 4) & 63));
    #pragma unroll
    for (int k = 0; k < 4; k++)
        out[k] = (win[2 + k] - 8.f * win[3 + k] + 8.f * win[5 + k] - win[6 + k])
               * (1.f / 12.f) * invpx;
}
__device__ __forceinline__ void dy4(float* out, const float* __restrict__ f, const P4& p) {
    float a[4], b[4], c[4], d[4];
    ld4(a, f, p.i + ((pidxN(p.h,     32) - p.h) << 6));
    ld4(b, f, p.i + ((pidxN(p.h + 1, 32) - p.h) << 6));
    ld4(c, f, p.i + ((pidxN(p.h + 3, 32) - p.h) << 6));
    ld4(d, f, p.i + ((pidxN(p.h + 4, 32) - p.h) << 6));
    #pragma unroll
    for (int k = 0; k < 4; k++)
        out[k] = (-a[k] + 8.f * b[k] - 8.f * c[k] + d[k]) * (1.f / 12.f) * (1.f / PIXYc);
}
__device__ __forceinline__ void dz4(float* out, const float* __restrict__ f, const P4& p) {
    float a[4], b[4], c[4], d[4];
    ld4(a, f, p.i + ((pidxN(p.v,     13) - p.v) << 11));
    ld4(b, f, p.i + ((pidxN(p.v + 1, 13) - p.v) << 11));
    ld4(c, f, p.i + ((pidxN(p.v + 3, 13) - p.v) << 11));
    ld4(d, f, p.i + ((pidxN(p.v + 4, 13) - p.v) << 11));
    float r = 1.f / (12.f * c_DZ[p.v]);
    #pragma unroll
    for (int k = 0; k < 4; k++)
        out[k] = (-a[k] + 8.f * b[k] - 8.f * c[k] + d[k]) * r;
}

// fused first derivs + mixing (composite 2nd-derivative stencils)
__device__ __forceinline__ void derivs_mix(const float* __restrict__ f, const P4& p,
                                           float invpx,
                                           float* d1x, float* d1y, float* d1z, float* mix) {
    // ---- x ----
    float win[12];
    int rb = p.i - p.w0;
    ld4(win,     f, rb + ((p.w0 + 60) & 63));
    ld4(win + 4, f, p.i);
    ld4(win + 8, f, rb + ((p.w0 + 4) & 63));
    const float CXX[9] = {1.f, -16.f, 64.f, 16.f, -130.f, 16.f, 64.f, -16.f, 1.f};
    float ipx2 = invpx * invpx * (1.f / 144.f);
    #pragma unroll
    for (int k = 0; k < 4; k++) {
        d1x[k] = (win[2 + k] - 8.f * win[3 + k] + 8.f * win[5 + k] - win[6 + k])
               * (1.f / 12.f) * invpx;
        float xx = 0.f;
        #pragma unroll
        for (int j = 0; j < 9; j++) xx += CXX[j] * win[k + j];
        mix[k] = KHc * (xx * ipx2);
    }
    // ---- y band ----
    {
        int s0 = pidxN(p.h, 32) - p.h + 4;
        int s1 = pidxN(p.h + 1, 32) - p.h + 4;
        int s2 = pidxN(p.h + 3, 32) - p.h + 4;
        int s3 = pidxN(p.h + 4, 32) - p.h + 4;
        const float* Wrow = g_Wy[p.h];
        float rows[9][4];
        #pragma unroll
        for (int j = 0; j < 9; j++) {
            int r = p.h - 4 + j;
            int rc = r < 0 ? 0 : (r > 31 ? 31 : r);
            ld4(rows[j], f, p.i + ((rc - p.h) << 6));
        }
        float acc2[4] = {0.f, 0.f, 0.f, 0.f};
        float acc1[4] = {0.f, 0.f, 0.f, 0.f};
        #pragma unroll
        for (int j = 0; j < 9; j++) {
            float w2 = Wrow[j];
            float c1 = (j == s0 ? -1.f : 0.f) + (j == s1 ? 8.f : 0.f)
                     + (j == s2 ? -8.f : 0.f) + (j == s3 ? 1.f : 0.f);
            #pragma unroll
            for (int k = 0; k < 4; k++) { acc2[k] += w2 * rows[j][k]; acc1[k] += c1 * rows[j][k]; }
        }
        #pragma unroll
        for (int k = 0; k < 4; k++) {
            d1y[k] = acc1[k] * (1.f / 12.f) * (1.f / PIXYc);
            mix[k] += KHc * acc2[k];
        }
    }
    // ---- z band ----
    {
        int s0 = pidxN(p.v, 13) - p.v + 4;
        int s1 = pidxN(p.v + 1, 13) - p.v + 4;
        int s2 = pidxN(p.v + 3, 13) - p.v + 4;
        int s3 = pidxN(p.v + 4, 13) - p.v + 4;
        const float* Wrow = g_Wz[p.v];
        float rows[9][4];
        #pragma unroll
        for (int j = 0; j < 9; j++) {
            int r = p.v - 4 + j;
            int rc = r < 0 ? 0 : (r > 12 ? 12 : r);
            ld4(rows[j], f, p.i + ((rc - p.v) << 11));
        }
        float acc2[4] = {0.f, 0.f, 0.f, 0.f};
        float acc1[4] = {0.f, 0.f, 0.f, 0.f};
        #pragma unroll
        for (int j = 0; j < 9; j++) {
            float w2 = Wrow[j];
            float c1 = (j == s0 ? -1.f : 0.f) + (j == s1 ? 8.f : 0.f)
                     + (j == s2 ? -8.f : 0.f) + (j == s3 ? 1.f : 0.f);
            #pragma unroll
            for (int k = 0; k < 4; k++) { acc2[k] += w2 * rows[j][k]; acc1[k] += c1 * rows[j][k]; }
        }
        float rz = 1.f / (12.f * c_DZ[p.v]);
        #pragma unroll
        for (int k = 0; k < 4; k++) {
            d1z[k] = acc1[k] * rz;
            mix[k] += KVc * acc2[k];
        }
    }
}

// per-warp reduce + subslot atomic
__device__ __forceinline__ void warpRedMM(float mn, float mx, int smn, int smx) {
    #pragma unroll
    for (int o = 16; o; o >>= 1) {
        mn = fminf(mn, __shfl_xor_sync(0xffffffffu, mn, o));
        mx = fmaxf(mx, __shfl_xor_sync(0xffffffffu, mx, o));
    }
    if ((threadIdx.x & 31) == 0) {
        int sub = (blockIdx.x * 4 + (threadIdx.x >> 5)) & 31;
        atomicMinF(&g_redp[smn][sub], mn);
        atomicMaxF(&g_redp[smx][sub], mx);
    }
}

// 256-thread-block reduction (bnapply) -> subslot atomics
__device__ __forceinline__ void blockRed256(float vmn, float vmx, float vsum,
                                            int smn, int smx, int ssum) {
    __shared__ float sh[24];
    __syncthreads();
    #pragma unroll
    for (int o = 16; o; o >>= 1) {
        vmn  = fminf(vmn, __shfl_xor_sync(0xffffffffu, vmn, o));
        vmx  = fmaxf(vmx, __shfl_xor_sync(0xffffffffu, vmx, o));
        vsum += __shfl_xor_sync(0xffffffffu, vsum, o);
    }
    int lane = threadIdx.x & 31, wid = threadIdx.x >> 5;
    if (lane == 0) { sh[wid] = vmn; sh[8 + wid] = vmx; sh[16 + wid] = vsum; }
    __syncthreads();
    if (threadIdx.x == 0) {
        float a = sh[0], b = sh[8], s = sh[16];
        #pragma unroll
        for (int k = 1; k < 8; k++) { a = fminf(a, sh[k]); b = fmaxf(b, sh[8 + k]); s += sh[16 + k]; }
        int sub = blockIdx.x & 31;
        atomicMinF(&g_redp[smn][sub], a);
        atomicMaxF(&g_redp[smx][sub], b);
        atomicAdd(&g_redp[ssum][sub], s);
    }
}

// ---------------- init: tables + reduction slots ----------------
__global__ void k_init() {
    int t = threadIdx.x;
    if (t < 32) {
        double lat = (90.0 - (double)(t + 1) * (180.0 / 33.0)) * M_PI / 180.0;
        float px = (float)(2.0 * M_PI * 6371000.0 * cos(lat) / 64.0);
        g_invpx[t] = 1.f / px;
        g_fcor[t]  = 2.0f * OMEGAc * sinf((float)lat);
    }
    if (t < 32) {
        float w[9];
        #pragma unroll
        for (int j = 0; j < 9; j++) w[j] = 0.f;
        const int   off[4] = {0, 1, 3, 4};
        const float co[4]  = {-1.f, 8.f, -8.f, 1.f};
        for (int m = 0; m < 4; m++) {
            int r1 = pidxN(t + off[m], 32);
            for (int n = 0; n < 4; n++) {
                int r0 = pidxN(r1 + off[n], 32);
                w[r0 - t + 4] += co[m] * co[n];
            }
        }
        float sc = 1.f / (144.f * PIXYc * PIXYc);
        for (int j = 0; j < 9; j++) g_Wy[t][j] = w[j] * sc;
    }
    if (t < 13) {
        float w[9];
        #pragma unroll
        for (int j = 0; j < 9; j++) w[j] = 0.f;
        const int   off[4] = {0, 1, 3, 4};
        const float co[4]  = {-1.f, 8.f, -8.f, 1.f};
        for (int m = 0; m < 4; m++) {
            int r1 = pidxN(t + off[m], 13);
            for (int n = 0; n < 4; n++) {
                int r0 = pidxN(r1 + off[n], 13);
                w[r0 - t + 4] += co[m] * co[n] / (c_DZ[t] * c_DZ[r1]);
            }
        }
        for (int j = 0; j < 9; j++) g_Wz[t][j] = w[j] * (1.f / 144.f);
    }
    float inf = __int_as_float(0x7f800000);
    for (int l = t; l < 27 * 32; l += 64) {
        int s = l >> 5, j = l & 31;
        float v;
        if (s < 5) v = inf;
        else if (s < 10) v = -inf;
        else if (s < 15) v = 0.f;
        else if (s == 15) v = inf;
        else if (s == 16) v = -inf;
        else if (s < 22) v = inf;
        else v = -inf;
        g_redp[s][j] = v;
    }
}

// collapse sub-slots -> g_red
__global__ void k_collapse(int lo, int hi) {
    int lane = threadIdx.x;
    for (int s = lo; s <= hi; s++) {
        float v = g_redp[s][lane];
        bool isSum = (s >= 10 && s <= 14);
        bool isMax = (s >= 5 && s <= 9) || s == 16 || s >= 22;
        #pragma unroll
        for (int o = 16; o; o >>= 1) {
            float u = __shfl_xor_sync(0xffffffffu, v, o);
            v = isSum ? v + u : (isMax ? fmaxf(v, u) : fminf(v, u));
        }
        if (lane == 0) g_red[s] = v;
    }
}

// ============ conv3x3, register-tiled FFMA2 + cp.async pipeline ============
template <int CI, int CO, int WHICH>
__global__ void __launch_bounds__(64) k_conv(const float* __restrict__ xin,
                                             const float* __restrict__ wt,
                                             const float* __restrict__ bias) {
    __shared__ __align__(16) float  xs[2][8][10][68];
    __shared__ __align__(16) float2 ws[8][9][8];
    const float* __restrict__ src = (WHICH == 0) ? xin : (const float*)g_o65;
    float* dst = (WHICH == 0) ? g_h : g_o2;

    const int tid = threadIdx.x;
    const int s = tid & 3, h = (tid >> 2) & 7, g = tid >> 5;
    const int y0 = blockIdx.y * 8, b = blockIdx.z, co0 = blockIdx.x * 8;
    const int NCH = (CI + 7) / 8;

    for (int l = tid; l < 2 * 8 * 10; l += 64) {
        int bu = l / 80, rem = l % 80;
        int ci = rem / 10, row = rem % 10;
        xs[bu][ci][row][0]  = 0.f;
        xs[bu][ci][row][65] = 0.f;
    }

    u64 acc[4][8];
    #pragma unroll
    for (int k = 0; k < 4; k++)
        #pragma unroll
        for (int j = 0; j < 8; j++) acc[k][j] = 0ull;

    const int cix = tid & 7;
    const int wv0 = tid >> 3;
    float wreg[9];

    #define W_LOAD(c0)                                                        \
        _Pragma("unroll")                                                     \
        for (int m = 0; m < 9; m++) {                                         \
            int l = tid + 64 * m;                                             \
            int col = l & 7, rest = l >> 3;                                   \
            int tap = rest % 9, ci = rest / 9;                                \
            bool ok = (co0 + col) < CO && ((c0) + ci) < CI;                   \
            wreg[m] = ok ? wt[((co0 + col) * CI + (c0) + ci) * 9 + tap] : 0.f;\
        }
    #define W_STS()                                                           \
        _Pragma("unroll")                                                     \
        for (int m = 0; m < 9; m++) {                                         \
            int l = tid + 64 * m;                                             \
            int col = l & 7, rest = l >> 3;                                   \
            int tap = rest % 9, ci = rest / 9;                                \
            ws[ci][tap][col] = make_float2(wreg[m], wreg[m]);                 \
        }
    #define X_PREF(bu, c0)                                                    \
        {                                                                     \
            bool civ = ((c0) + cix) < CI;                                     \
            const float* sb = src + (((size_t)(b * CI + (c0) + cix)) << 11);  \
            _Pragma("unroll")                                                 \
            for (int row = 0; row < 10; row++) {                              \
                int hg = y0 - 1 + row;                                        \
                int ok = (civ && hg >= 0 && hg < 32) ? 4 : 0;                 \
                int hgc = hg < 0 ? 0 : (hg > 31 ? 31 : hg);                   \
                const float* sp = sb + hgc * 64 + wv0;                        \
                unsigned dp = (unsigned)__cvta_generic_to_shared(             \
                                  &xs[bu][cix][row][1 + wv0]);                \
                _Pragma("unroll")                                             \
                for (int jj = 0; jj < 8; jj++)                                \
                    asm volatile("cp.async.ca.shared.global [%0], [%1], 4, %2;" \
                                 :: "r"(dp + jj * 32), "l"(sp + jj * 8), "r"(ok)); \
            }                                                                 \
        }

    W_LOAD(0);
    X_PREF(0, 0);
    asm volatile("cp.async.commit_group;");

    int buf = 0;
    for (int c = 0; c < NCH; c++) {
        asm volatile("cp.async.wait_group 0;");
        __syncthreads();
        W_STS();
        if (c + 1 < NCH) { W_LOAD((c + 1) * 8); }
        __syncthreads();
        if (c + 1 < NCH) {
            X_PREF(buf ^ 1, (c + 1) * 8);
            asm volatile("cp.async.commit_group;");
        }
        for (int ci = 0; ci < 8; ci++) {
            #pragma unroll
            for (int r = 0; r < 3; r++) {
                const float* xr = &xs[buf][ci][h + r][16 * s];
                ulonglong2 q0 = *reinterpret_cast<const ulonglong2*>(xr);
                ulonglong2 q1 = *reinterpret_cast<const ulonglong2*>(xr + 4);
                ulonglong2 q2 = *reinterpret_cast<const ulonglong2*>(xr + 8);
                ulonglong2 q3 = *reinterpret_cast<const ulonglong2*>(xr + 12);
                u64 e8 = *reinterpret_cast<const u64*>(xr + 16);
                u64 E[9] = {q0.x, q0.y, q1.x, q1.y, q2.x, q2.y, q3.x, q3.y, e8};
                u64 O[8];
                #pragma unroll
                for (int j = 0; j < 8; j++) O[j] = oddpair(E[j], E[j + 1]);
                ulonglong2 wA  = *reinterpret_cast<const ulonglong2*>(&ws[ci][r * 3 + 0][g * 4]);
                ulonglong2 wA2 = *reinterpret_cast<const ulonglong2*>(&ws[ci][r * 3 + 0][g * 4 + 2]);
                ulonglong2 wB  = *reinterpret_cast<const ulonglong2*>(&ws[ci][r * 3 + 1][g * 4]);
                ulonglong2 wB2 = *reinterpret_cast<const ulonglong2*>(&ws[ci][r * 3 + 1][g * 4 + 2]);
                ulonglong2 wC  = *reinterpret_cast<const ulonglong2*>(&ws[ci][r * 3 + 2][g * 4]);
                ulonglong2 wC2 = *reinterpret_cast<const ulonglong2*>(&ws[ci][r * 3 + 2][g * 4 + 2]);
                #pragma unroll
                for (int j = 0; j < 8; j++) {
                    fm2(acc[0][j], E[j], wA.x);  fm2(acc[0][j], O[j], wB.x);  fm2(acc[0][j], E[j + 1], wC.x);
                    fm2(acc[1][j], E[j], wA.y);  fm2(acc[1][j], O[j], wB.y);  fm2(acc[1][j], E[j + 1], wC.y);
                    fm2(acc[2][j], E[j], wA2.x); fm2(acc[2][j], O[j], wB2.x); fm2(acc[2][j], E[j + 1], wC2.x);
                    fm2(acc[3][j], E[j], wA2.y); fm2(acc[3][j], O[j], wB2.y); fm2(acc[3][j], E[j + 1], wC2.y);
                }
            }
        }
        buf ^= 1;
    }
    #undef W_LOAD
    #undef W_STS
    #undef X_PREF

    #pragma unroll
    for (int k = 0; k < 4; k++) {
        int co = co0 + g * 4 + k;
        if (co < CO) {
            float bs = bias[co];
            float* dp = &dst[(((b * CO + co) << 5) + (y0 + h)) * 64 + 16 * s];
            #pragma unroll
            for (int m = 0; m < 4; m++) {
                float a0, a1, b0, b1;
                upk2(a0, a1, acc[k][2 * m]);
                upk2(b0, b1, acc[k][2 * m + 1]);
                float4 o = make_float4(a0 + bs, a1 + bs, b0 + bs, b1 + bs);
                *reinterpret_cast<float4*>(dp + 4 * m) = o;
            }
        }
    }
}

// ---------------- BN stats ----------------
template <int C, int WHICH>
__global__ void k_bnstats() {
    const float* src = (WHICH == 0) ? g_h : g_o2;
    int c = blockIdx.x;
    float s = 0.f, s2 = 0.f;
    for (int e = threadIdx.x; e < 4096; e += 256) {
        int b = e >> 9, j = (e & 511) << 2;
        float4 v4 = *reinterpret_cast<const float4*>(&src[((b * C + c) << 11) + j]);
        s  += v4.x + v4.y + v4.z + v4.w;
        s2 += v4.x * v4.x + v4.y * v4.y + v4.z * v4.z + v4.w * v4.w;
    }
    __shared__ float sh[16];
    #pragma unroll
    for (int o = 16; o; o >>= 1) {
        s  += __shfl_xor_sync(0xffffffffu, s, o);
        s2 += __shfl_xor_sync(0xffffffffu, s2, o);
    }
    int lane = threadIdx.x & 31, wid = threadIdx.x >> 5;
    if (lane == 0) { sh[wid] = s; sh[8 + wid] = s2; }
    __syncthreads();
    if (threadIdx.x == 0) {
        float a = sh[0], b2 = sh[8];
        #pragma unroll
        for (int k = 1; k < 8; k++) { a += sh[k]; b2 += sh[8 + k]; }
        float m = a * (1.f / 16384.f);
        float var = b2 * (1.f / 16384.f) - m * m;
        if (WHICH == 0) { g_m65[c] = m;  g_is65[c] = rsqrtf(var + 1e-5f); }
        else            { g_m256[c] = m; g_is256[c] = rsqrtf(var + 1e-5f); }
    }
}

// ---------------- BN apply + split + field reduce ----------------
__global__ void k_bnapply(const float* gz, const float* bz, const float* gq, const float* bq,
                          const float* gu, const float* bu, const float* gv, const float* bv,
                          const float* gt, const float* bt) {
    int i4 = blockIdx.x * 256 + threadIdx.x;
    int i  = i4 << 2;
    int bc = i >> 11;
    int c = bc % 65, b = bc / 65;
    int hw = i & 2047;
    int F = c / 13, v = c % 13;
    const float* ga = F == 0 ? gz : F == 1 ? gq : F == 2 ? gu : F == 3 ? gv : gt;
    const float* be = F == 0 ? bz : F == 1 ? bq : F == 2 ? bu : F == 3 ? bv : bt;
    float gsc = g_is65[c] * ga[v];
    float m   = g_m65[c];
    float bia = be[v];
    float4 hv = *reinterpret_cast<const float4*>(&g_h[i]);
    float4 o;
    o.x = (hv.x - m) * gsc + bia; o.y = (hv.y - m) * gsc + bia;
    o.z = (hv.z - m) * gsc + bia; o.w = (hv.w - m) * gsc + bia;
    *reinterpret_cast<float4*>(&g_fld[F][((b * 13 + v) << 11) + hw]) = o;
    float mn = fminf(fminf(o.x, o.y), fminf(o.z, o.w));
    float mx = fmaxf(fmaxf(o.x, o.y), fmaxf(o.z, o.w));
    float sm = o.x + o.y + o.z + o.w;
    blockRed256(mn, mx, sm, F, 5 + F, 10 + F);
}

// ---------------- base derivs (frozen fields only) + sarg reduce ----------------
__global__ void __launch_bounds__(128) k_basederiv() {
    int i4 = blockIdx.x * 128 + threadIdx.x;
    P4 p = decode4(i4);
    float invpx = g_invpx[p.h];
    float t1[4];
    dx4(t1, g_fld[0], p, invpx); st4(g_zx, p.i, t1);
    dy4(t1, g_fld[0], p);        st4(g_zy, p.i, t1);
    dz4(t1, g_fld[0], p);        st4(g_zz, p.i, t1);
    dx4(t1, g_fld[2], p, invpx); st4(g_ux, p.i, t1);
    dy4(t1, g_fld[3], p);        st4(g_vy, p.i, t1);
    float tt[4];
    ld4(tt, g_fld[4], p.i);
    float smn = __int_as_float(0x7f800000), smx = -smn;
    #pragma unroll
    for (int k = 0; k < 4; k++) {
        float tc = tt[k] - 273.15f;
        float s = 17.67f * tc / avoid_inf1(tc + 243.5f);
        smn = fminf(smn, s); smx = fmaxf(smx, s);
    }
    warpRedMM(smn, smx, 15, 16);
}

// ---------------- w_vel column integral ----------------
__global__ void k_wvel() {
    int j = blockIdx.x * 128 + threadIdx.x;
    int b = j >> 11, hw = j & 2047;
    float s = 0.f;
    for (int v = 0; v < 13; v++) {
        int off = ((b * 13 + v) << 11) + hw;
        s += c_DZ[v] * (g_ux[off] + g_vy[off]);
        g_w[off] = -s;
    }
}

// ---------------- RK stage for u,v (light register footprint) ----------------
__global__ void __launch_bounds__(128) k_stage_uv(int stage) {
    int i4 = blockIdx.x * 128 + threadIdx.x;
    P4 p = decode4(i4);
    float invpx = g_invpx[p.h];
    float fco = g_fcor[p.h];

    const float* fu = stage == 0 ? g_fld[2] : g_sua;
    const float* fv = stage == 0 ? g_fld[3] : g_sva;

    float w_[4], u0[4], v0[4], ua[4], va[4];
    ld4(w_, g_w, p.i);
    ld4(u0, g_fld[2], p.i); ld4(v0, g_fld[3], p.i);
    ld4(ua, fu, p.i); ld4(va, fv, p.i);

    float d1x[4], d1y[4], d1z[4], mix[4], tmp[4];
    float ku[4], kv[4];

    // ---- u
    derivs_mix(fu, p, invpx, d1x, d1y, d1z, mix);
    ld4(tmp, g_ux, p.i);
    #pragma unroll
    for (int k = 0; k < 4; k++)
        ku[k] = mix[k] - ua[k] * tmp[k] - va[k] * d1y[k] - w_[k] * d1z[k] + fco * va[k];
    ld4(tmp, g_zx, p.i);
    #pragma unroll
    for (int k = 0; k < 4; k++) ku[k] -= tmp[k];

    // ---- v
    derivs_mix(fv, p, invpx, d1x, d1y, d1z, mix);
    ld4(tmp, g_vy, p.i);
    #pragma unroll
    for (int k = 0; k < 4; k++)
        kv[k] = mix[k] - ua[k] * d1x[k] - va[k] * tmp[k] - w_[k] * d1z[k] - fco * ua[k];
    ld4(tmp, g_zy, p.i);
    #pragma unroll
    for (int k = 0; k < 4; k++) kv[k] -= tmp[k];

    if (stage == 0) {
        st4(g_accu, p.i, ku); st4(g_accv, p.i, kv);
        float s1[4], s2[4];
        #pragma unroll
        for (int k = 0; k < 4; k++) {
            s1[k] = u0[k] + 0.5f * DTs * ku[k];
            s2[k] = v0[k] + 0.5f * DTs * kv[k];
        }
        st4(g_sua, p.i, s1); st4(g_sva, p.i, s2);
    } else if (stage == 1 || stage == 2) {
        float au[4], av[4];
        ld4(au, g_accu, p.i); ld4(av, g_accv, p.i);
        #pragma unroll
        for (int k = 0; k < 4; k++) { au[k] += 2.f * ku[k]; av[k] += 2.f * kv[k]; }
        st4(g_accu, p.i, au); st4(g_accv, p.i, av);
        float cdt = (stage == 1) ? 0.5f * DTs : DTs;
        float s1[4], s2[4];
        #pragma unroll
        for (int k = 0; k < 4; k++) {
            s1[k] = u0[k] + cdt * ku[k];
            s2[k] = v0[k] + cdt * kv[k];
        }
        st4(g_sua, p.i, s1); st4(g_sva, p.i, s2);
    } else {
        float au[4], av[4];
        ld4(au, g_accu, p.i); ld4(av, g_accv, p.i);
        #pragma unroll
        for (int k = 0; k < 4; k++) {
            au[k] = (au[k] + ku[k]) * (DTs / 6.f);
            av[k] = (av[k] + kv[k]) * (DTs / 6.f);
        }
        st4(g_accu, p.i, au); st4(g_accv, p.i, av);
        float umn = fminf(fminf(au[0], au[1]), fminf(au[2], au[3]));
        float umx = fmaxf(fmaxf(au[0], au[1]), fmaxf(au[2], au[3]));
        float vmn = fminf(fminf(av[0], av[1]), fminf(av[2], av[3]));
        float vmx = fmaxf(fmaxf(av[0], av[1]), fmaxf(av[2], av[3]));
        warpRedMM(umn, umx, 19, 24);
        warpRedMM(vmn, vmx, 20, 25);
    }
}

// ---------------- RK stage for t (+rate and q tendency at stage 0) ----------------
__global__ void __launch_bounds__(128) k_stage_t(int stage) {
    int i4 = blockIdx.x * 128 + threadIdx.x;
    P4 p = decode4(i4);
    float invpx = g_invpx[p.h];

    const float* ft = stage == 0 ? g_fld[4] : g_sta;

    float w_[4], zz[4], u0[4], v0[4], t0[4], ta[4];
    ld4(w_, g_w, p.i); ld4(zz, g_zz, p.i);
    ld4(u0, g_fld[2], p.i); ld4(v0, g_fld[3], p.i); ld4(t0, g_fld[4], p.i);
    ld4(ta, ft, p.i);

    float rate[4];
    if (stage == 0) {
        float q_[4]; ld4(q_, g_fld[1], p.i);
        float smn = g_red[15], smx = g_red[16];
        float rcp = 6.48f / (smx - smn);
        #pragma unroll
        for (int k = 0; k < 4; k++) {
            float rho = -1.f / avoid_inf1(zz[k]);
            float pr  = rho * RGASc * t0[k];
            float tc  = t0[k] - 273.15f;
            float s   = 17.67f * tc / avoid_inf1(tc + 243.5f);
            float sc  = (s - smn) * rcp - 3.47f;
            float es  = 6.112f * expf(sc) * 100.f;
            float qs  = fmaxf(0.622f * es / avoid_inf1(pr - 0.378f * es), 1e-6f);
            float rh  = q_[k] / avoid_inf1(qs);
            rate[k]   = (rh > 0.8f) ? (q_[k] - 0.8f * qs) * (1.f / DTs) : 0.f;
        }
        st4(g_rate, p.i, rate);
    } else {
        ld4(rate, g_rate, p.i);
    }

    float d1x[4], d1y[4], d1z[4], mix[4];
    float kt[4];

    derivs_mix(ft, p, invpx, d1x, d1y, d1z, mix);
    float iprs = 1.f / c_PRS[p.v];
    #pragma unroll
    for (int k = 0; k < 4; k++) {
        kt[k] = mix[k] - u0[k] * d1x[k] - v0[k] * d1y[k] - w_[k] * d1z[k];
        float taabs = ta[k] + 273.15f;
        float t2 = taabs * taabs;
        float t5 = t2 * t2 * taabs;
        float rc = -(EMISc * SIGMAc * RDc / (CPc * 100.f)) * t5 * iprs;
        kt[k] += -((LVc + 1.f) / CPc) * zz[k] * w_[k] + rc + rate[k] * (LVc / CPc);
    }

    if (stage == 0) {
        st4(g_acct, p.i, kt);
        float s3[4];
        #pragma unroll
        for (int k = 0; k < 4; k++) s3[k] = t0[k] + 0.5f * DTs * kt[k];
        st4(g_sta, p.i, s3);
        // ---- q tendency (base field q)
        derivs_mix(g_fld[1], p, invpx, d1x, d1y, d1z, mix);
        float qt[4];
        #pragma unroll
        for (int k = 0; k < 4; k++)
            qt[k] = (mix[k] - u0[k] * d1x[k] - v0[k] * d1y[k] - w_[k] * d1z[k] - rate[k]) * DTs;
        st4(g_dq, p.i, qt);
        float qmn = fminf(fminf(qt[0], qt[1]), fminf(qt[2], qt[3]));
        float qmx = fmaxf(fmaxf(qt[0], qt[1]), fmaxf(qt[2], qt[3]));
        warpRedMM(qmn, qmx, 18, 23);
    } else if (stage == 1 || stage == 2) {
        float at[4];
        ld4(at, g_acct, p.i);
        #pragma unroll
        for (int k = 0; k < 4; k++) at[k] += 2.f * kt[k];
        st4(g_acct, p.i, at);
        float cdt = (stage == 1) ? 0.5f * DTs : DTs;
        float s3[4];
        #pragma unroll
        for (int k = 0; k < 4; k++) s3[k] = t0[k] + cdt * kt[k];
        st4(g_sta, p.i, s3);
    } else {
        st4(g_k4t, p.i, kt);
        float at[4];
        ld4(at, g_acct, p.i);
        #pragma unroll
        for (int k = 0; k < 4; k++) at[k] = (at[k] + kt[k]) * (DTs / 6.f);
        st4(g_acct, p.i, at);
        float tmn = fminf(fminf(at[0], at[1]), fminf(at[2], at[3]));
        float tmx = fmaxf(fmaxf(at[0], at[1]), fmaxf(at[2], at[3]));
        warpRedMM(tmn, tmx, 21, 26);
    }
}

// ---------------- z tendency column integral ----------------
__global__ void k_zt() {
    int j = blockIdx.x * 128 + threadIdx.x;
    int b = j >> 11, hw = j & 2047;
    float s = 0.f;
    float inf = __int_as_float(0x7f800000);
    float mn = inf, mx = -inf;
    for (int v = 0; v < 13; v++) {
        int off = ((b * 13 + v) << 11) + hw;
        s += c_DZ[v] * (-RGASc / c_PRS[v]) * g_k4t[off];
        float d = s * DTs;
        g_dzd[off] = d;
        mn = fminf(mn, d); mx = fmaxf(mx, d);
    }
    #pragma unroll
    for (int o = 16; o; o >>= 1) {
        mn = fminf(mn, __shfl_xor_sync(0xffffffffu, mn, o));
        mx = fmaxf(mx, __shfl_xor_sync(0xffffffffu, mx, o));
    }
    if ((threadIdx.x & 31) == 0) {
        int sub = (blockIdx.x * 4 + (threadIdx.x >> 5)) & 31;
        atomicMinF(&g_redp[17][sub], mn);
        atomicMaxF(&g_redp[22][sub], mx);
    }
}

// ---------------- apply scale_diff + coef mix -> g_o65 ----------------
__global__ void k_apply65(const float* __restrict__ coef) {
    int i4 = blockIdx.x * 256 + threadIdx.x;
    int i  = i4 << 2;
    int bc = i >> 11;
    int c = bc % 65, b = bc / 65;
    int hw = i & 2047;
    int F = c / 13, v = c % 13;
    int fi = ((b * 13 + v) << 11) + hw;
    const float* dsrc = F == 0 ? g_dzd : F == 1 ? g_dq :
                        F == 2 ? g_accu : F == 3 ? g_accv : g_acct;
    float4 base = *reinterpret_cast<const float4*>(&g_fld[F][fi]);
    float4 diff = *reinterpret_cast<const float4*>(&dsrc[fi]);
    float mn = g_red[F], mx = g_red[5 + F];
    float me = g_red[10 + F] * (1.f / 212992.f);
    float a = (mn - me) * 0.05f;
    float bb = (mx - me) * 0.05f;
    float dmn = g_red[17 + F], dmx = g_red[22 + F];
    float sc = (bb - a) / (dmx - dmn);
    float4 cf = *reinterpret_cast<const float4*>(&coef[(c << 11) + hw]);
    float4 hv = *reinterpret_cast<const float4*>(&g_h[i]);
    float4 o;
    o.x = cf.x * (base.x + (diff.x - dmn) * sc + a) + (1.f - cf.x) * hv.x;
    o.y = cf.y * (base.y + (diff.y - dmn) * sc + a) + (1.f - cf.y) * hv.y;
    o.z = cf.z * (base.z + (diff.z - dmn) * sc + a) + (1.f - cf.z) * hv.z;
    o.w = cf.w * (base.w + (diff.w - dmn) * sc + a) + (1.f - cf.w) * hv.w;
    *reinterpret_cast<float4*>(&g_o65[i]) = o;
}

// ---------------- final: BN(o2) + x ----------------
__global__ void k_final(const float* __restrict__ x, const float* __restrict__ gblk,
                        const float* __restrict__ bblk, float* __restrict__ out) {
    int i4 = blockIdx.x * 256 + threadIdx.x;
    int i  = i4 << 2;
    int c = (i >> 11) & 255;
    float gsc = g_is256[c] * gblk[c];
    float m = g_m256[c], bia = bblk[c];
    float4 o2 = *reinterpret_cast<const float4*>(&g_o2[i]);
    float4 xv = *reinterpret_cast<const float4*>(&x[i]);
    float4 o;
    o.x = (o2.x - m) * gsc + bia + xv.x;
    o.y = (o2.y - m) * gsc + bia + xv.y;
    o.z = (o2.z - m) * gsc + bia + xv.z;
    o.w = (o2.w - m) * gsc + bia + xv.w;
    *reinterpret_cast<float4*>(&out[i]) = o;
}

// ---------------- launcher ----------------
extern "C" void kernel_launch(void* const* d_in, const int* in_sizes, int n_in,
                              void* d_out, int out_size) {
    const float* x        = (const float*)d_in[0];
    const float* w_norm   = (const float*)d_in[1];
    const float* b_norm   = (const float*)d_in[2];
    const float* w_innorm = (const float*)d_in[3];
    const float* b_innorm = (const float*)d_in[4];
    const float* coef     = (const float*)d_in[5];
    const float* gz = (const float*)d_in[6];  const float* bz = (const float*)d_in[7];
    const float* gq = (const float*)d_in[8];  const float* bq = (const float*)d_in[9];
    const float* gu = (const float*)d_in[10]; const float* bu = (const float*)d_in[11];
    const float* gv = (const float*)d_in[12]; const float* bv = (const float*)d_in[13];
    const float* gt = (const float*)d_in[14]; const float* bt = (const float*)d_in[15];
    const float* gblk = (const float*)d_in[16];
    const float* bblk = (const float*)d_in[17];
    float* out = (float*)d_out;

    k_init<<<1, 64>>>();
    k_conv<256, 65, 0><<<dim3(9, 4, 8), 64>>>(x, w_norm, b_norm);
    k_bnstats<65, 0><<<65, 256>>>();
    k_bnapply<<<NHE / 1024, 256>>>(gz, bz, gq, bq, gu, bu, gv, bv, gt, bt);
    k_basederiv<<<GSTG, 128>>>();
    k_collapse<<<1, 32>>>(15, 16);
    k_wvel<<<128, 128>>>();
    for (int s = 0; s < 4; s++) {
        k_stage_uv<<<GSTG, 128>>>(s);
        k_stage_t<<<GSTG, 128>>>(s);
    }
    k_zt<<<128, 128>>>();
    k_collapse<<<1, 32>>>(0, 26);
    k_apply65<<<NHE / 1024, 256>>>(coef);
    k_conv<65, 256, 1><<<dim3(32, 4, 8), 64>>>(nullptr, w_innorm, b_innorm);
    k_bnstats<256, 1><<<256, 256>>>();
    k_final<<<NOE / 1024, 256>>>(x, gblk, bblk, out);
}

// round 12
// speedup vs baseline: 1.0913x; 1.0913x over previous
#include <cuda_runtime.h>
#include <math.h>

// ---------------- dims ----------------
#define NFE 212992              // 8*13*32*64
#define NHE 1064960             // 8*65*32*64
#define NOE 4194304             // 8*256*32*64
#define GSTG 416                // NFE/4/128 : 128-thread blocks, 4 elems/thread

// ---------------- physics consts ----------------
#define DTs    300.0f
#define KHc    15.0f
#define KVc    0.1f
#define LVc    2.5e6f
#define CPc    1005.0f
#define RGASc  8.314f
#define RDc    287.0f
#define OMEGAc 7.29e-5f
#define EMISc  0.7f
#define SIGMAc 5.67e-8f
#define PIXYc  ((float)(M_PI * 6371000.0 / 33.0))

__constant__ float c_DZ[13]  = {50.f,50.f,50.f,50.f,50.f,75.f,100.f,100.f,100.f,125.f,112.f,75.f,75.f};
__constant__ float c_PRS[13] = {50.f,100.f,150.f,200.f,250.f,300.f,400.f,500.f,600.f,700.f,850.f,925.f,1000.f};

// ---------------- scratch ----------------
__device__ float g_h[NHE], g_o65[NHE];
__device__ float g_o2[NOE];
__device__ float g_fld[5][NFE];                        // z,q,u,v,t post-BN
__device__ float g_zx[NFE], g_zy[NFE], g_zz[NFE], g_ux[NFE], g_vy[NFE];
__device__ float g_w[NFE], g_rate[NFE];
__device__ float g_sua[NFE], g_sva[NFE], g_sta[NFE];   // RK stage fields u,v,t
__device__ float g_accu[NFE], g_accv[NFE], g_acct[NFE];
__device__ float g_k4t[NFE], g_dq[NFE], g_dzd[NFE];
__device__ float g_m65[65], g_is65[65], g_m256[256], g_is256[256];
__device__ float g_red[27];
__device__ float g_redp[27][32];                       // sub-slotted reductions
__device__ float g_invpx[32], g_fcor[32];
__device__ float g_Wy[32][9];                          // composite d_y(d_y) band
__device__ float g_Wz[13][9];                          // composite d_z(d_z) band

// red slots: 0..4 field min (z,q,u,v,t); 5..9 field max; 10..14 field sum;
//            15 sarg min; 16 sarg max; 17..21 diff min (z,q,u,v,t); 22..26 diff max

// ---------------- helpers ----------------
__device__ __forceinline__ void atomicMinF(float* a, float v) {
    if (v >= 0.f) atomicMin((int*)a, __float_as_int(v));
    else          atomicMax((unsigned int*)a, __float_as_uint(v));
}
__device__ __forceinline__ void atomicMaxF(float* a, float v) {
    if (v >= 0.f) atomicMax((int*)a, __float_as_int(v));
    else          atomicMin((unsigned int*)a, __float_as_uint(v));
}
__device__ __forceinline__ float avoid_inf1(float t) {
    if (t == 0.f) return 1.f;
    if (fabsf(t) < 1.f) return t > 0.f ? 1.f : -1.f;
    return t;
}

typedef unsigned long long u64;
__device__ __forceinline__ u64 pk2(float lo, float hi) {
    u64 r; asm("mov.b64 %0,{%1,%2};" : "=l"(r) : "f"(lo), "f"(hi)); return r;
}
__device__ __forceinline__ void fm2(u64& d, u64 a, u64 b) {
    asm("fma.rn.f32x2 %0,%1,%2,%0;" : "+l"(d) : "l"(a), "l"(b));
}
__device__ __forceinline__ void upk2(float& lo, float& hi, u64 v) {
    asm("mov.b64 {%0,%1},%2;" : "=f"(lo), "=f"(hi) : "l"(v));
}
__device__ __forceinline__ u64 oddpair(u64 a, u64 b) {
    u64 r;
    asm("{\n\t.reg .f32 al, ah, bl, bh;\n\t"
        "mov.b64 {al,ah}, %1;\n\t"
        "mov.b64 {bl,bh}, %2;\n\t"
        "mov.b64 %0, {ah,bl};\n\t}"
        : "=l"(r) : "l"(a), "l"(b));
    return r;
}

__device__ __forceinline__ int pidxN(int m, int n) {   // block-replicate pad index
    return m < 2 ? m : (m < n + 2 ? m - 2 : m - 4);
}

// ---------------- 4-wide packet ----------------
struct P4 { int i, v, h, w0; };
__device__ __forceinline__ P4 decode4(int i4) {
    P4 p; int i = i4 << 2;
    p.i = i; p.w0 = i & 63; p.h = (i >> 6) & 31;
    p.v = (i >> 11) % 13;
    return p;
}
__device__ __forceinline__ void ld4(float* d, const float* __restrict__ f, int idx) {
    float4 t = *reinterpret_cast<const float4*>(f + idx);
    d[0] = t.x; d[1] = t.y; d[2] = t.z; d[3] = t.w;
}
__device__ __forceinline__ void st4(float* f, int idx, const float* s) {
    *reinterpret_cast<float4*>(f + idx) = make_float4(s[0], s[1], s[2], s[3]);
}
__device__ __forceinline__ void dx4(float* out, const float* __restrict__ f,
                                    const P4& p, float invpx) {
    float win[12];
    int rb = p.i - p.w0;
    ld4(win,     f, rb + ((p.w0 + 60) & 63));
    ld4(win + 4, f, p.i);
    ld4(win + 8, f, rb + ((p.w0 + 4) & 63));
    #pragma unroll
    for (int k = 0; k < 4; k++)
        out[k] = (win[2 + k] - 8.f * win[3 + k] + 8.f * win[5 + k] - win[6 + k])
               * (1.f / 12.f) * invpx;
}
__device__ __forceinline__ void dy4(float* out, const float* __restrict__ f, const P4& p) {
    float a[4], b[4], c[4], d[4];
    ld4(a, f, p.i + ((pidxN(p.h,     32) - p.h) << 6));
    ld4(b, f, p.i + ((pidxN(p.h + 1, 32) - p.h) << 6));
    ld4(c, f, p.i + ((pidxN(p.h + 3, 32) - p.h) << 6));
    ld4(d, f, p.i + ((pidxN(p.h + 4, 32) - p.h) << 6));
    #pragma unroll
    for (int k = 0; k < 4; k++)
        out[k] = (-a[k] + 8.f * b[k] - 8.f * c[k] + d[k]) * (1.f / 12.f) * (1.f / PIXYc);
}
__device__ __forceinline__ void dz4(float* out, const float* __restrict__ f, const P4& p) {
    float a[4], b[4], c[4], d[4];
    ld4(a, f, p.i + ((pidxN(p.v,     13) - p.v) << 11));
    ld4(b, f, p.i + ((pidxN(p.v + 1, 13) - p.v) << 11));
    ld4(c, f, p.i + ((pidxN(p.v + 3, 13) - p.v) << 11));
    ld4(d, f, p.i + ((pidxN(p.v + 4, 13) - p.v) << 11));
    float r = 1.f / (12.f * c_DZ[p.v]);
    #pragma unroll
    for (int k = 0; k < 4; k++)
        out[k] = (-a[k] + 8.f * b[k] - 8.f * c[k] + d[k]) * r;
}

// fused first derivs + mixing (composite 2nd-derivative stencils)
__device__ __forceinline__ void derivs_mix(const float* __restrict__ f, const P4& p,
                                           float invpx,
                                           float* d1x, float* d1y, float* d1z, float* mix) {
    // ---- x ----
    float win[12];
    int rb = p.i - p.w0;
    ld4(win,     f, rb + ((p.w0 + 60) & 63));
    ld4(win + 4, f, p.i);
    ld4(win + 8, f, rb + ((p.w0 + 4) & 63));
    const float CXX[9] = {1.f, -16.f, 64.f, 16.f, -130.f, 16.f, 64.f, -16.f, 1.f};
    float ipx2 = invpx * invpx * (1.f / 144.f);
    #pragma unroll
    for (int k = 0; k < 4; k++) {
        d1x[k] = (win[2 + k] - 8.f * win[3 + k] + 8.f * win[5 + k] - win[6 + k])
               * (1.f / 12.f) * invpx;
        float xx = 0.f;
        #pragma unroll
        for (int j = 0; j < 9; j++) xx += CXX[j] * win[k + j];
        mix[k] = KHc * (xx * ipx2);
    }
    // ---- y band ----
    {
        int s0 = pidxN(p.h, 32) - p.h + 4;
        int s1 = pidxN(p.h + 1, 32) - p.h + 4;
        int s2 = pidxN(p.h + 3, 32) - p.h + 4;
        int s3 = pidxN(p.h + 4, 32) - p.h + 4;
        const float* Wrow = g_Wy[p.h];
        float rows[9][4];
        #pragma unroll
        for (int j = 0; j < 9; j++) {
            int r = p.h - 4 + j;
            int rc = r < 0 ? 0 : (r > 31 ? 31 : r);
            ld4(rows[j], f, p.i + ((rc - p.h) << 6));
        }
        float acc2[4] = {0.f, 0.f, 0.f, 0.f};
        float acc1[4] = {0.f, 0.f, 0.f, 0.f};
        #pragma unroll
        for (int j = 0; j < 9; j++) {
            float w2 = Wrow[j];
            float c1 = (j == s0 ? -1.f : 0.f) + (j == s1 ? 8.f : 0.f)
                     + (j == s2 ? -8.f : 0.f) + (j == s3 ? 1.f : 0.f);
            #pragma unroll
            for (int k = 0; k < 4; k++) { acc2[k] += w2 * rows[j][k]; acc1[k] += c1 * rows[j][k]; }
        }
        #pragma unroll
        for (int k = 0; k < 4; k++) {
            d1y[k] = acc1[k] * (1.f / 12.f) * (1.f / PIXYc);
            mix[k] += KHc * acc2[k];
        }
    }
    // ---- z band ----
    {
        int s0 = pidxN(p.v, 13) - p.v + 4;
        int s1 = pidxN(p.v + 1, 13) - p.v + 4;
        int s2 = pidxN(p.v + 3, 13) - p.v + 4;
        int s3 = pidxN(p.v + 4, 13) - p.v + 4;
        const float* Wrow = g_Wz[p.v];
        float rows[9][4];
        #pragma unroll
        for (int j = 0; j < 9; j++) {
            int r = p.v - 4 + j;
            int rc = r < 0 ? 0 : (r > 12 ? 12 : r);
            ld4(rows[j], f, p.i + ((rc - p.v) << 11));
        }
        float acc2[4] = {0.f, 0.f, 0.f, 0.f};
        float acc1[4] = {0.f, 0.f, 0.f, 0.f};
        #pragma unroll
        for (int j = 0; j < 9; j++) {
            float w2 = Wrow[j];
            float c1 = (j == s0 ? -1.f : 0.f) + (j == s1 ? 8.f : 0.f)
                     + (j == s2 ? -8.f : 0.f) + (j == s3 ? 1.f : 0.f);
            #pragma unroll
            for (int k = 0; k < 4; k++) { acc2[k] += w2 * rows[j][k]; acc1[k] += c1 * rows[j][k]; }
        }
        float rz = 1.f / (12.f * c_DZ[p.v]);
        #pragma unroll
        for (int k = 0; k < 4; k++) {
            d1z[k] = acc1[k] * rz;
            mix[k] += KVc * acc2[k];
        }
    }
}

// per-warp reduce + subslot atomic
__device__ __forceinline__ void warpRedMM(float mn, float mx, int smn, int smx) {
    #pragma unroll
    for (int o = 16; o; o >>= 1) {
        mn = fminf(mn, __shfl_xor_sync(0xffffffffu, mn, o));
        mx = fmaxf(mx, __shfl_xor_sync(0xffffffffu, mx, o));
    }
    if ((threadIdx.x & 31) == 0) {
        int sub = (blockIdx.x * 4 + (threadIdx.x >> 5)) & 31;
        atomicMinF(&g_redp[smn][sub], mn);
        atomicMaxF(&g_redp[smx][sub], mx);
    }
}

// 256-thread-block reduction (bnapply) -> subslot atomics
__device__ __forceinline__ void blockRed256(float vmn, float vmx, float vsum,
                                            int smn, int smx, int ssum) {
    __shared__ float sh[24];
    __syncthreads();
    #pragma unroll
    for (int o = 16; o; o >>= 1) {
        vmn  = fminf(vmn, __shfl_xor_sync(0xffffffffu, vmn, o));
        vmx  = fmaxf(vmx, __shfl_xor_sync(0xffffffffu, vmx, o));
        vsum += __shfl_xor_sync(0xffffffffu, vsum, o);
    }
    int lane = threadIdx.x & 31, wid = threadIdx.x >> 5;
    if (lane == 0) { sh[wid] = vmn; sh[8 + wid] = vmx; sh[16 + wid] = vsum; }
    __syncthreads();
    if (threadIdx.x == 0) {
        float a = sh[0], b = sh[8], s = sh[16];
        #pragma unroll
        for (int k = 1; k < 8; k++) { a = fminf(a, sh[k]); b = fmaxf(b, sh[8 + k]); s += sh[16 + k]; }
        int sub = blockIdx.x & 31;
        atomicMinF(&g_redp[smn][sub], a);
        atomicMaxF(&g_redp[smx][sub], b);
        atomicAdd(&g_redp[ssum][sub], s);
    }
}

// ---------------- init: tables + reduction slots ----------------
__global__ void k_init() {
    int t = threadIdx.x;
    if (t < 32) {
        double lat = (90.0 - (double)(t + 1) * (180.0 / 33.0)) * M_PI / 180.0;
        float px = (float)(2.0 * M_PI * 6371000.0 * cos(lat) / 64.0);
        g_invpx[t] = 1.f / px;
        g_fcor[t]  = 2.0f * OMEGAc * sinf((float)lat);
    }
    if (t < 32) {
        float w[9];
        #pragma unroll
        for (int j = 0; j < 9; j++) w[j] = 0.f;
        const int   off[4] = {0, 1, 3, 4};
        const float co[4]  = {-1.f, 8.f, -8.f, 1.f};
        for (int m = 0; m < 4; m++) {
            int r1 = pidxN(t + off[m], 32);
            for (int n = 0; n < 4; n++) {
                int r0 = pidxN(r1 + off[n], 32);
                w[r0 - t + 4] += co[m] * co[n];
            }
        }
        float sc = 1.f / (144.f * PIXYc * PIXYc);
        for (int j = 0; j < 9; j++) g_Wy[t][j] = w[j] * sc;
    }
    if (t < 13) {
        float w[9];
        #pragma unroll
        for (int j = 0; j < 9; j++) w[j] = 0.f;
        const int   off[4] = {0, 1, 3, 4};
        const float co[4]  = {-1.f, 8.f, -8.f, 1.f};
        for (int m = 0; m < 4; m++) {
            int r1 = pidxN(t + off[m], 13);
            for (int n = 0; n < 4; n++) {
                int r0 = pidxN(r1 + off[n], 13);
                w[r0 - t + 4] += co[m] * co[n] / (c_DZ[t] * c_DZ[r1]);
            }
        }
        for (int j = 0; j < 9; j++) g_Wz[t][j] = w[j] * (1.f / 144.f);
    }
    float inf = __int_as_float(0x7f800000);
    for (int l = t; l < 27 * 32; l += 64) {
        int s = l >> 5, j = l & 31;
        float v;
        if (s < 5) v = inf;
        else if (s < 10) v = -inf;
        else if (s < 15) v = 0.f;
        else if (s == 15) v = inf;
        else if (s == 16) v = -inf;
        else if (s < 22) v = inf;
        else v = -inf;
        g_redp[s][j] = v;
    }
}

// collapse sub-slots -> g_red
__global__ void k_collapse(int lo, int hi) {
    int lane = threadIdx.x;
    for (int s = lo; s <= hi; s++) {
        float v = g_redp[s][lane];
        bool isSum = (s >= 10 && s <= 14);
        bool isMax = (s >= 5 && s <= 9) || s == 16 || s >= 22;
        #pragma unroll
        for (int o = 16; o; o >>= 1) {
            float u = __shfl_xor_sync(0xffffffffu, v, o);
            v = isSum ? v + u : (isMax ? fmaxf(v, u) : fminf(v, u));
        }
        if (lane == 0) g_red[s] = v;
    }
}

// ============ conv3x3: 128 threads (all 4 SMSPs), co_tile 8, h_tile 16 ============
// ci chunk = 4, double-buffered 4-byte cp.async (alignment-safe), smem 41.5 KB.
// conv1 grid (9,2,8)=144 blocks (single wave); conv2 grid (32,2,8)=512.
template <int CI, int CO, int WHICH>
__global__ void __launch_bounds__(128) k_conv(const float* __restrict__ xin,
                                              const float* __restrict__ wt,
                                              const float* __restrict__ bias) {
    __shared__ __align__(16) float  xs[2][4][18][68];
    __shared__ __align__(16) float2 ws[4][9][8];
    const float* __restrict__ src = (WHICH == 0) ? xin : (const float*)g_o65;
    float* dst = (WHICH == 0) ? g_h : g_o2;

    const int tid = threadIdx.x;
    const int s = tid & 3, h = (tid >> 2) & 15, g = tid >> 6;
    const int y0 = blockIdx.y * 16, b = blockIdx.z, co0 = blockIdx.x * 8;
    const int NCH = (CI + 3) / 4;

    // zero halo columns 0 and 65 in both buffers
    for (int l = tid; l < 2 * 4 * 18; l += 128) {
        int bu = l / 72, rem = l % 72;
        int ci = rem / 18, row = rem % 18;
        xs[bu][ci][row][0]  = 0.f;
        xs[bu][ci][row][65] = 0.f;
    }

    u64 acc[4][8];
    #pragma unroll
    for (int k = 0; k < 4; k++)
        #pragma unroll
        for (int j = 0; j < 8; j++) acc[k][j] = 0ull;

    // x-prefetch mapping: thread owns ci=tid&3 and a 2-column pair, all 18 rows
    const int cix  = tid & 3;
    const int colb = (tid >> 2) * 2;       // 0,2,...,62
    float wreg[3];

    #define W_LOAD(c0)                                                        \
        _Pragma("unroll")                                                     \
        for (int m = 0; m < 3; m++) {                                         \
            int l = tid + 128 * m;                                            \
            int col = l & 7, rest = l >> 3;                                   \
            int tap = rest % 9, ci = rest / 9;                                \
            bool ok = l < 288 && (co0 + col) < CO && ((c0) + ci) < CI;        \
            wreg[m] = ok ? wt[((co0 + col) * CI + (c0) + ci) * 9 + tap] : 0.f;\
        }
    #define W_STS()                                                           \
        _Pragma("unroll")                                                     \
        for (int m = 0; m < 3; m++) {                                         \
            int l = tid + 128 * m;                                            \
            if (l < 288) {                                                    \
                int col = l & 7, rest = l >> 3;                               \
                int tap = rest % 9, ci = rest / 9;                            \
                ws[ci][tap][col] = make_float2(wreg[m], wreg[m]);             \
            }                                                                 \
        }
    #define X_PREF(bu, c0)                                                    \
        {                                                                     \
            bool civ = ((c0) + cix) < CI;                                     \
            const float* sb = src + (((size_t)(b * CI + (c0) + cix)) << 11);  \
            _Pragma("unroll")                                                 \
            for (int row = 0; row < 18; row++) {                              \
                int hg = y0 - 1 + row;                                        \
                int ok = (civ && hg >= 0 && hg < 32) ? 4 : 0;                 \
                int hgc = hg < 0 ? 0 : (hg > 31 ? 31 : hg);                   \
                const float* sp = sb + hgc * 64 + colb;                       \
                unsigned dp = (unsigned)__cvta_generic_to_shared(             \
                                  &xs[bu][cix][row][1 + colb]);               \
                asm volatile("cp.async.ca.shared.global [%0], [%1], 4, %2;"   \
                             :: "r"(dp), "l"(sp), "r"(ok));                   \
                asm volatile("cp.async.ca.shared.global [%0], [%1], 4, %2;"   \
                             :: "r"(dp + 4), "l"(sp + 1), "r"(ok));           \
            }                                                                 \
        }

    W_LOAD(0);
    X_PREF(0, 0);
    asm volatile("cp.async.commit_group;");

    int buf = 0;
    for (int c = 0; c < NCH; c++) {
        asm volatile("cp.async.wait_group 0;");
        __syncthreads();
        W_STS();
        if (c + 1 < NCH) { W_LOAD((c + 1) * 4); }
        __syncthreads();
        if (c + 1 < NCH) {
            X_PREF(buf ^ 1, (c + 1) * 4);
            asm volatile("cp.async.commit_group;");
        }
        #pragma unroll
        for (int ci = 0; ci < 4; ci++) {
            #pragma unroll
            for (int r = 0; r < 3; r++) {
                const float* xr = &xs[buf][ci][h + r][16 * s];
                ulonglong2 q0 = *reinterpret_cast<const ulonglong2*>(xr);
                ulonglong2 q1 = *reinterpret_cast<const ulonglong2*>(xr + 4);
                ulonglong2 q2 = *reinterpret_cast<const ulonglong2*>(xr + 8);
                ulonglong2 q3 = *reinterpret_cast<const ulonglong2*>(xr + 12);
                u64 e8 = *reinterpret_cast<const u64*>(xr + 16);
                u64 E[9] = {q0.x, q0.y, q1.x, q1.y, q2.x, q2.y, q3.x, q3.y, e8};
                u64 O[8];
                #pragma unroll
                for (int j = 0; j < 8; j++) O[j] = oddpair(E[j], E[j + 1]);
                ulonglong2 wA  = *reinterpret_cast<const ulonglong2*>(&ws[ci][r * 3 + 0][g * 4]);
                ulonglong2 wA2 = *reinterpret_cast<const ulonglong2*>(&ws[ci][r * 3 + 0][g * 4 + 2]);
                ulonglong2 wB  = *reinterpret_cast<const ulonglong2*>(&ws[ci][r * 3 + 1][g * 4]);
                ulonglong2 wB2 = *reinterpret_cast<const ulonglong2*>(&ws[ci][r * 3 + 1][g * 4 + 2]);
                ulonglong2 wC  = *reinterpret_cast<const ulonglong2*>(&ws[ci][r * 3 + 2][g * 4]);
                ulonglong2 wC2 = *reinterpret_cast<const ulonglong2*>(&ws[ci][r * 3 + 2][g * 4 + 2]);
                #pragma unroll
                for (int j = 0; j < 8; j++) {
                    fm2(acc[0][j], E[j], wA.x);  fm2(acc[0][j], O[j], wB.x);  fm2(acc[0][j], E[j + 1], wC.x);
                    fm2(acc[1][j], E[j], wA.y);  fm2(acc[1][j], O[j], wB.y);  fm2(acc[1][j], E[j + 1], wC.y);
                    fm2(acc[2][j], E[j], wA2.x); fm2(acc[2][j], O[j], wB2.x); fm2(acc[2][j], E[j + 1], wC2.x);
                    fm2(acc[3][j], E[j], wA2.y); fm2(acc[3][j], O[j], wB2.y); fm2(acc[3][j], E[j + 1], wC2.y);
                }
            }
        }
        buf ^= 1;
    }
    #undef W_LOAD
    #undef W_STS
    #undef X_PREF

    #pragma unroll
    for (int k = 0; k < 4; k++) {
        int co = co0 + g * 4 + k;
        if (co < CO) {
            float bs = bias[co];
            float* dp = &dst[(((b * CO + co) << 5) + (y0 + h)) * 64 + 16 * s];
            #pragma unroll
            for (int m = 0; m < 4; m++) {
                float a0, a1, b0, b1;
                upk2(a0, a1, acc[k][2 * m]);
                upk2(b0, b1, acc[k][2 * m + 1]);
                float4 o = make_float4(a0 + bs, a1 + bs, b0 + bs, b1 + bs);
                *reinterpret_cast<float4*>(dp + 4 * m) = o;
            }
        }
    }
}

// ---------------- BN stats ----------------
template <int C, int WHICH>
__global__ void k_bnstats() {
    const float* src = (WHICH == 0) ? g_h : g_o2;
    int c = blockIdx.x;
    float s = 0.f, s2 = 0.f;
    for (int e = threadIdx.x; e < 4096; e += 256) {
        int b = e >> 9, j = (e & 511) << 2;
        float4 v4 = *reinterpret_cast<const float4*>(&src[((b * C + c) << 11) + j]);
        s  += v4.x + v4.y + v4.z + v4.w;
        s2 += v4.x * v4.x + v4.y * v4.y + v4.z * v4.z + v4.w * v4.w;
    }
    __shared__ float sh[16];
    #pragma unroll
    for (int o = 16; o; o >>= 1) {
        s  += __shfl_xor_sync(0xffffffffu, s, o);
        s2 += __shfl_xor_sync(0xffffffffu, s2, o);
    }
    int lane = threadIdx.x & 31, wid = threadIdx.x >> 5;
    if (lane == 0) { sh[wid] = s; sh[8 + wid] = s2; }
    __syncthreads();
    if (threadIdx.x == 0) {
        float a = sh[0], b2 = sh[8];
        #pragma unroll
        for (int k = 1; k < 8; k++) { a += sh[k]; b2 += sh[8 + k]; }
        float m = a * (1.f / 16384.f);
        float var = b2 * (1.f / 16384.f) - m * m;
        if (WHICH == 0) { g_m65[c] = m;  g_is65[c] = rsqrtf(var + 1e-5f); }
        else            { g_m256[c] = m; g_is256[c] = rsqrtf(var + 1e-5f); }
    }
}

// ---------------- BN apply + split + field reduce ----------------
__global__ void k_bnapply(const float* gz, const float* bz, const float* gq, const float* bq,
                          const float* gu, const float* bu, const float* gv, const float* bv,
                          const float* gt, const float* bt) {
    int i4 = blockIdx.x * 256 + threadIdx.x;
    int i  = i4 << 2;
    int bc = i >> 11;
    int c = bc % 65, b = bc / 65;
    int hw = i & 2047;
    int F = c / 13, v = c % 13;
    const float* ga = F == 0 ? gz : F == 1 ? gq : F == 2 ? gu : F == 3 ? gv : gt;
    const float* be = F == 0 ? bz : F == 1 ? bq : F == 2 ? bu : F == 3 ? bv : bt;
    float gsc = g_is65[c] * ga[v];
    float m   = g_m65[c];
    float bia = be[v];
    float4 hv = *reinterpret_cast<const float4*>(&g_h[i]);
    float4 o;
    o.x = (hv.x - m) * gsc + bia; o.y = (hv.y - m) * gsc + bia;
    o.z = (hv.z - m) * gsc + bia; o.w = (hv.w - m) * gsc + bia;
    *reinterpret_cast<float4*>(&g_fld[F][((b * 13 + v) << 11) + hw]) = o;
    float mn = fminf(fminf(o.x, o.y), fminf(o.z, o.w));
    float mx = fmaxf(fmaxf(o.x, o.y), fmaxf(o.z, o.w));
    float sm = o.x + o.y + o.z + o.w;
    blockRed256(mn, mx, sm, F, 5 + F, 10 + F);
}

// ---------------- base derivs (frozen fields only) + sarg reduce ----------------
__global__ void __launch_bounds__(128) k_basederiv() {
    int i4 = blockIdx.x * 128 + threadIdx.x;
    P4 p = decode4(i4);
    float invpx = g_invpx[p.h];
    float t1[4];
    dx4(t1, g_fld[0], p, invpx); st4(g_zx, p.i, t1);
    dy4(t1, g_fld[0], p);        st4(g_zy, p.i, t1);
    dz4(t1, g_fld[0], p);        st4(g_zz, p.i, t1);
    dx4(t1, g_fld[2], p, invpx); st4(g_ux, p.i, t1);
    dy4(t1, g_fld[3], p);        st4(g_vy, p.i, t1);
    float tt[4];
    ld4(tt, g_fld[4], p.i);
    float smn = __int_as_float(0x7f800000), smx = -smn;
    #pragma unroll
    for (int k = 0; k < 4; k++) {
        float tc = tt[k] - 273.15f;
        float s = 17.67f * tc / avoid_inf1(tc + 243.5f);
        smn = fminf(smn, s); smx = fmaxf(smx, s);
    }
    warpRedMM(smn, smx, 15, 16);
}

// ---------------- w_vel column integral ----------------
__global__ void k_wvel() {
    int j = blockIdx.x * 128 + threadIdx.x;
    int b = j >> 11, hw = j & 2047;
    float s = 0.f;
    for (int v = 0; v < 13; v++) {
        int off = ((b * 13 + v) << 11) + hw;
        s += c_DZ[v] * (g_ux[off] + g_vy[off]);
        g_w[off] = -s;
    }
}

// ---------------- fused RK stage (unified, R8 best config) ----------------
__global__ void __launch_bounds__(128) k_stage(int stage) {
    int i4 = blockIdx.x * 128 + threadIdx.x;
    P4 p = decode4(i4);
    float invpx = g_invpx[p.h];
    float fco = g_fcor[p.h];

    const float* fu = stage == 0 ? g_fld[2] : g_sua;
    const float* fv = stage == 0 ? g_fld[3] : g_sva;
    const float* ft = stage == 0 ? g_fld[4] : g_sta;

    float w_[4], zz[4], u0[4], v0[4], t0[4];
    ld4(w_, g_w, p.i); ld4(zz, g_zz, p.i);
    ld4(u0, g_fld[2], p.i); ld4(v0, g_fld[3], p.i); ld4(t0, g_fld[4], p.i);
    float ua[4], va[4], ta[4];
    ld4(ua, fu, p.i); ld4(va, fv, p.i); ld4(ta, ft, p.i);

    float rate[4];
    if (stage == 0) {
        float q_[4]; ld4(q_, g_fld[1], p.i);
        float smn = g_red[15], smx = g_red[16];
        float rcp = 6.48f / (smx - smn);
        #pragma unroll
        for (int k = 0; k < 4; k++) {
            float rho = -1.f / avoid_inf1(zz[k]);
            float pr  = rho * RGASc * t0[k];
            float tc  = t0[k] - 273.15f;
            float s   = 17.67f * tc / avoid_inf1(tc + 243.5f);
            float sc  = (s - smn) * rcp - 3.47f;
            float es  = 6.112f * expf(sc) * 100.f;
            float qs  = fmaxf(0.622f * es / avoid_inf1(pr - 0.378f * es), 1e-6f);
            float rh  = q_[k] / avoid_inf1(qs);
            rate[k]   = (rh > 0.8f) ? (q_[k] - 0.8f * qs) * (1.f / DTs) : 0.f;
        }
        st4(g_rate, p.i, rate);
    } else {
        ld4(rate, g_rate, p.i);
    }

    float d1x[4], d1y[4], d1z[4], mix[4], tmp[4];
    float ku[4], kv[4], kt[4];

    // ---- u
    derivs_mix(fu, p, invpx, d1x, d1y, d1z, mix);
    ld4(tmp, g_ux, p.i);
    #pragma unroll
    for (int k = 0; k < 4; k++)
        ku[k] = mix[k] - ua[k] * tmp[k] - va[k] * d1y[k] - w_[k] * d1z[k] + fco * va[k];
    ld4(tmp, g_zx, p.i);
    #pragma unroll
    for (int k = 0; k < 4; k++) ku[k] -= tmp[k];

    // ---- v
    derivs_mix(fv, p, invpx, d1x, d1y, d1z, mix);
    ld4(tmp, g_vy, p.i);
    #pragma unroll
    for (int k = 0; k < 4; k++)
        kv[k] = mix[k] - ua[k] * d1x[k] - va[k] * tmp[k] - w_[k] * d1z[k] - fco * ua[k];
    ld4(tmp, g_zy, p.i);
    #pragma unroll
    for (int k = 0; k < 4; k++) kv[k] -= tmp[k];

    // ---- t (advected by base u0,v0)
    derivs_mix(ft, p, invpx, d1x, d1y, d1z, mix);
    float iprs = 1.f / c_PRS[p.v];
    #pragma unroll
    for (int k = 0; k < 4; k++) {
        kt[k] = mix[k] - u0[k] * d1x[k] - v0[k] * d1y[k] - w_[k] * d1z[k];
        float taabs = ta[k] + 273.15f;
        float t2 = taabs * taabs;
        float t5 = t2 * t2 * taabs;
        float rc = -(EMISc * SIGMAc * RDc / (CPc * 100.f)) * t5 * iprs;
        kt[k] += -((LVc + 1.f) / CPc) * zz[k] * w_[k] + rc + rate[k] * (LVc / CPc);
    }

    if (stage == 0) {
        st4(g_accu, p.i, ku); st4(g_accv, p.i, kv); st4(g_acct, p.i, kt);
        float s1[4], s2[4], s3[4];
        #pragma unroll
        for (int k = 0; k < 4; k++) {
            s1[k] = u0[k] + 0.5f * DTs * ku[k];
            s2[k] = v0[k] + 0.5f * DTs * kv[k];
            s3[k] = t0[k] + 0.5f * DTs * kt[k];
        }
        st4(g_sua, p.i, s1); st4(g_sva, p.i, s2); st4(g_sta, p.i, s3);
        derivs_mix(g_fld[1], p, invpx, d1x, d1y, d1z, mix);
        float qt[4];
        #pragma unroll
        for (int k = 0; k < 4; k++)
            qt[k] = (mix[k] - u0[k] * d1x[k] - v0[k] * d1y[k] - w_[k] * d1z[k] - rate[k]) * DTs;
        st4(g_dq, p.i, qt);
        float qmn = fminf(fminf(qt[0], qt[1]), fminf(qt[2], qt[3]));
        float qmx = fmaxf(fmaxf(qt[0], qt[1]), fmaxf(qt[2], qt[3]));
        warpRedMM(qmn, qmx, 18, 23);
    } else if (stage == 1 || stage == 2) {
        float au[4], av[4], at[4];
        ld4(au, g_accu, p.i); ld4(av, g_accv, p.i); ld4(at, g_acct, p.i);
        #pragma unroll
        for (int k = 0; k < 4; k++) { au[k] += 2.f * ku[k]; av[k] += 2.f * kv[k]; at[k] += 2.f * kt[k]; }
        st4(g_accu, p.i, au); st4(g_accv, p.i, av); st4(g_acct, p.i, at);
        float cdt = (stage == 1) ? 0.5f * DTs : DTs;
        float s1[4], s2[4], s3[4];
        #pragma unroll
        for (int k = 0; k < 4; k++) {
            s1[k] = u0[k] + cdt * ku[k];
            s2[k] = v0[k] + cdt * kv[k];
            s3[k] = t0[k] + cdt * kt[k];
        }
        st4(g_sua, p.i, s1); st4(g_sva, p.i, s2); st4(g_sta, p.i, s3);
    } else {
        st4(g_k4t, p.i, kt);
        float au[4], av[4], at[4];
        ld4(au, g_accu, p.i); ld4(av, g_accv, p.i); ld4(at, g_acct, p.i);
        #pragma unroll
        for (int k = 0; k < 4; k++) {
            au[k] = (au[k] + ku[k]) * (DTs / 6.f);
            av[k] = (av[k] + kv[k]) * (DTs / 6.f);
            at[k] = (at[k] + kt[k]) * (DTs / 6.f);
        }
        st4(g_accu, p.i, au); st4(g_accv, p.i, av); st4(g_acct, p.i, at);
        float umn = fminf(fminf(au[0], au[1]), fminf(au[2], au[3]));
        float umx = fmaxf(fmaxf(au[0], au[1]), fmaxf(au[2], au[3]));
        float vmn = fminf(fminf(av[0], av[1]), fminf(av[2], av[3]));
        float vmx = fmaxf(fmaxf(av[0], av[1]), fmaxf(av[2], av[3]));
        float tmn = fminf(fminf(at[0], at[1]), fminf(at[2], at[3]));
        float tmx = fmaxf(fmaxf(at[0], at[1]), fmaxf(at[2], at[3]));
        warpRedMM(umn, umx, 19, 24);
        warpRedMM(vmn, vmx, 20, 25);
        warpRedMM(tmn, tmx, 21, 26);
    }
}

// ---------------- z tendency column integral ----------------
__global__ void k_zt() {
    int j = blockIdx.x * 128 + threadIdx.x;
    int b = j >> 11, hw = j & 2047;
    float s = 0.f;
    float inf = __int_as_float(0x7f800000);
    float mn = inf, mx = -inf;
    for (int v = 0; v < 13; v++) {
        int off = ((b * 13 + v) << 11) + hw;
        s += c_DZ[v] * (-RGASc / c_PRS[v]) * g_k4t[off];
        float d = s * DTs;
        g_dzd[off] = d;
        mn = fminf(mn, d); mx = fmaxf(mx, d);
    }
    #pragma unroll
    for (int o = 16; o; o >>= 1) {
        mn = fminf(mn, __shfl_xor_sync(0xffffffffu, mn, o));
        mx = fmaxf(mx, __shfl_xor_sync(0xffffffffu, mx, o));
    }
    if ((threadIdx.x & 31) == 0) {
        int sub = (blockIdx.x * 4 + (threadIdx.x >> 5)) & 31;
        atomicMinF(&g_redp[17][sub], mn);
        atomicMaxF(&g_redp[22][sub], mx);
    }
}

// ---------------- apply scale_diff + coef mix -> g_o65 ----------------
__global__ void k_apply65(const float* __restrict__ coef) {
    int i4 = blockIdx.x * 256 + threadIdx.x;
    int i  = i4 << 2;
    int bc = i >> 11;
    int c = bc % 65, b = bc / 65;
    int hw = i & 2047;
    int F = c / 13, v = c % 13;
    int fi = ((b * 13 + v) << 11) + hw;
    const float* dsrc = F == 0 ? g_dzd : F == 1 ? g_dq :
                        F == 2 ? g_accu : F == 3 ? g_accv : g_acct;
    float4 base = *reinterpret_cast<const float4*>(&g_fld[F][fi]);
    float4 diff = *reinterpret_cast<const float4*>(&dsrc[fi]);
    float mn = g_red[F], mx = g_red[5 + F];
    float me = g_red[10 + F] * (1.f / 212992.f);
    float a = (mn - me) * 0.05f;
    float bb = (mx - me) * 0.05f;
    float dmn = g_red[17 + F], dmx = g_red[22 + F];
    float sc = (bb - a) / (dmx - dmn);
    float4 cf = *reinterpret_cast<const float4*>(&coef[(c << 11) + hw]);
    float4 hv = *reinterpret_cast<const float4*>(&g_h[i]);
    float4 o;
    o.x = cf.x * (base.x + (diff.x - dmn) * sc + a) + (1.f - cf.x) * hv.x;
    o.y = cf.y * (base.y + (diff.y - dmn) * sc + a) + (1.f - cf.y) * hv.y;
    o.z = cf.z * (base.z + (diff.z - dmn) * sc + a) + (1.f - cf.z) * hv.z;
    o.w = cf.w * (base.w + (diff.w - dmn) * sc + a) + (1.f - cf.w) * hv.w;
    *reinterpret_cast<float4*>(&g_o65[i]) = o;
}

// ---------------- final: BN(o2) + x ----------------
__global__ void k_final(const float* __restrict__ x, const float* __restrict__ gblk,
                        const float* __restrict__ bblk, float* __restrict__ out) {
    int i4 = blockIdx.x * 256 + threadIdx.x;
    int i  = i4 << 2;
    int c = (i >> 11) & 255;
    float gsc = g_is256[c] * gblk[c];
    float m = g_m256[c], bia = bblk[c];
    float4 o2 = *reinterpret_cast<const float4*>(&g_o2[i]);
    float4 xv = *reinterpret_cast<const float4*>(&x[i]);
    float4 o;
    o.x = (o2.x - m) * gsc + bia + xv.x;
    o.y = (o2.y - m) * gsc + bia + xv.y;
    o.z = (o2.z - m) * gsc + bia + xv.z;
    o.w = (o2.w - m) * gsc + bia + xv.w;
    *reinterpret_cast<float4*>(&out[i]) = o;
}

// ---------------- launcher ----------------
extern "C" void kernel_launch(void* const* d_in, const int* in_sizes, int n_in,
                              void* d_out, int out_size) {
    const float* x        = (const float*)d_in[0];
    const float* w_norm   = (const float*)d_in[1];
    const float* b_norm   = (const float*)d_in[2];
    const float* w_innorm = (const float*)d_in[3];
    const float* b_innorm = (const float*)d_in[4];
    const float* coef     = (const float*)d_in[5];
    const float* gz = (const float*)d_in[6];  const float* bz = (const float*)d_in[7];
    const float* gq = (const float*)d_in[8];  const float* bq = (const float*)d_in[9];
    const float* gu = (const float*)d_in[10]; const float* bu = (const float*)d_in[11];
    const float* gv = (const float*)d_in[12]; const float* bv = (const float*)d_in[13];
    const float* gt = (const float*)d_in[14]; const float* bt = (const float*)d_in[15];
    const float* gblk = (const float*)d_in[16];
    const float* bblk = (const float*)d_in[17];
    float* out = (float*)d_out;

    k_init<<<1, 64>>>();
    k_conv<256, 65, 0><<<dim3(9, 2, 8), 128>>>(x, w_norm, b_norm);
    k_bnstats<65, 0><<<65, 256>>>();
    k_bnapply<<<NHE / 1024, 256>>>(gz, bz, gq, bq, gu, bu, gv, bv, gt, bt);
    k_basederiv<<<GSTG, 128>>>();
    k_collapse<<<1, 32>>>(15, 16);
    k_wvel<<<128, 128>>>();
    k_stage<<<GSTG, 128>>>(0);
    k_stage<<<GSTG, 128>>>(1);
    k_stage<<<GSTG, 128>>>(2);
    k_stage<<<GSTG, 128>>>(3);
    k_zt<<<128, 128>>>();
    k_collapse<<<1, 32>>>(0, 26);
    k_apply65<<<NHE / 1024, 256>>>(coef);
    k_conv<65, 256, 1><<<dim3(32, 2, 8), 128>>>(nullptr, w_innorm, b_innorm);
    k_bnstats<256, 1><<<256, 256>>>();
    k_final<<<NOE / 1024, 256>>>(x, gblk, bblk, out);
}